// round 17
// baseline (speedup 1.0000x reference)
#include <cuda_runtime.h>
#include <cuda_bf16.h>
#include <cstdint>

// Problem constants
#define T_STEPS 2048
#define BATCH   256
#define IN_DIM  64
#define HID     256
#define GROUPS  16
#define JCTAS   8
#define ROWS    16
#define THREADS 512

// smem layout (4-byte word offsets)
#define OFF_HHI  0          // h tile hi frags: 16 chunks x 32 lanes x 4 words = 2048
#define OFF_HLO  2048
#define OFF_XHI  4096       // x tile hi: 4 chunks x 32 x 4 = 512
#define OFF_XLO  4608
#define OFF_BLOH 5120       // W_hh lo frags: 16 warps x 3 gates x 4 chunks x 64 = 12288
#define OFF_BLOX 17408      // W_ih lo frags: 16 x 3 x 1 x 64 = 3072
#define OFF_PART 20480      // cross-warp partials: 3 sets x 128 lanes x 20 = 7680
#define SMEM_UNITS 28160
#define SMEM_BYTES (SMEM_UNITS*4)

// Device scratch
__device__ float g_hs[(size_t)T_STEPS * BATCH * HID];          // trajectory [T][B][H]
__device__ unsigned int g_hfrag_hi[2][GROUPS * 2048];          // h state, bf16x2 frag layout
__device__ unsigned int g_hfrag_lo[2][GROUPS * 2048];
__device__ unsigned int g_xfrag_hi[(size_t)T_STEPS * GROUPS * 512];
__device__ unsigned int g_xfrag_lo[(size_t)T_STEPS * GROUPS * 512];
__device__ unsigned int g_arr[GROUPS * 32];                    // per-group arrival counters

typedef unsigned long long ull;

// ---- helpers ----
__device__ __forceinline__ uint32_t packbf2(float f0, float f1) {   // f0 -> low half
    uint32_t r; asm("cvt.rn.bf16x2.f32 %0, %1, %2;" : "=r"(r) : "f"(f1), "f"(f0)); return r;
}
__device__ __forceinline__ float bfhi(float f) {
    return __bfloat162float(__float2bfloat16_rn(f));
}
__device__ __forceinline__ float2 unpackbf2(uint32_t u) {
    __nv_bfloat162 b = *reinterpret_cast<__nv_bfloat162*>(&u);
    return make_float2(__bfloat162float(b.x), __bfloat162float(b.y));
}
__device__ __forceinline__ float fast_sig(float x) {
    return __fdividef(1.f, 1.f + __expf(-x));
}
__device__ __forceinline__ float fast_tanh(float x) {
    float y; asm("tanh.approx.f32 %0, %1;" : "=f"(y) : "f"(x)); return y;
}
__device__ __forceinline__ unsigned int ld_acq(const unsigned int* p) {
    unsigned int v;
    asm volatile("ld.acquire.gpu.global.u32 %0, [%1];" : "=r"(v) : "l"(p));
    return v;
}
__device__ __forceinline__ void red_release(unsigned int* p) {
    asm volatile("red.release.gpu.global.add.u32 [%0], %1;" :: "l"(p), "r"(1u) : "memory");
}
__device__ __forceinline__ uint32_t smem_u32(const void* p) {
    uint32_t a;
    asm("{ .reg .u64 t; cvta.to.shared.u64 t, %1; cvt.u32.u64 %0, t; }" : "=r"(a) : "l"(p));
    return a;
}
__device__ __forceinline__ void cp_async16(uint32_t saddr, const void* gaddr) {
    asm volatile("cp.async.cg.shared.global [%0], [%1], 16;" :: "r"(saddr), "l"(gaddr) : "memory");
}
__device__ __forceinline__ void cp_async_commit_wait() {
    asm volatile("cp.async.commit_group;" ::: "memory");
    asm volatile("cp.async.wait_group 0;" ::: "memory");
}
// packed fp32x2 FMA (k_out)
__device__ __forceinline__ void fma2(ull& acc, ull a, ull b) {
    asm("fma.rn.f32x2 %0, %1, %2, %0;" : "+l"(acc) : "l"(a), "l"(b));
}
__device__ __forceinline__ float redpair(ull v) {
    float lo = __uint_as_float((unsigned int)(v & 0xffffffffULL));
    float hi = __uint_as_float((unsigned int)(v >> 32));
    return lo + hi;
}

// m16n8k16 bf16 mma, D += A*B
#define MMA16(D, A, B0, B1) \
    asm volatile("mma.sync.aligned.m16n8k16.row.col.f32.bf16.bf16.f32 " \
                 "{%0,%1,%2,%3},{%4,%5,%6,%7},{%8,%9},{%0,%1,%2,%3};" \
                 : "+f"(D[0]), "+f"(D[1]), "+f"(D[2]), "+f"(D[3]) \
                 : "r"((A).x), "r"((A).y), "r"((A).z), "r"((A).w), "r"(B0), "r"(B1))

// =====================================================================
// Pre-kernel: xs[t] = (t==0 ? 0 : input[t-1]) -> bf16 hi/lo frag arrays.
// =====================================================================
__global__ void __launch_bounds__(256) k_xprep(const float* __restrict__ input)
{
    size_t gid = (size_t)blockIdx.x * 256 + threadIdx.x;   // T*B*16 total
    int i4 = (int)(gid & 15);
    size_t tb = gid >> 4;
    int b = (int)(tb & 255);
    int t = (int)(tb >> 8);
    if (t >= T_STEPS) return;

    float vals[4];
    if (t == 0) {
        vals[0] = vals[1] = vals[2] = vals[3] = 0.f;
    } else {
        float4 v = *(const float4*)(input + (((size_t)(t - 1) * BATCH + b) * IN_DIM) + i4 * 4);
        vals[0] = v.x; vals[1] = v.y; vals[2] = v.z; vals[3] = v.w;
    }
    int grp = b >> 4, r = b & 15;
    size_t base = ((size_t)t * GROUPS + grp) * 512;
    #pragma unroll
    for (int pp = 0; pp < 2; pp++) {
        int p = i4 * 2 + pp;               // col pair index, cols 2p, 2p+1
        float v0 = vals[2 * pp], v1 = vals[2 * pp + 1];
        int chunk = p >> 3;
        int q_l = p & 3;
        int khalf = (p >> 2) & 1;
        size_t idx = base + (size_t)((chunk * 32 + (r & 7) * 4 + q_l) * 4 + (r >> 3) + 2 * khalf);
        g_xfrag_hi[idx] = packbf2(v0, v1);
        g_xfrag_lo[idx] = packbf2(v0 - bfhi(v0), v1 - bfhi(v1));
    }
}

// =====================================================================
// Persistent recurrent kernel: bf16 m16n8k16 mma (3-product split),
// 512 threads, K quartered across warps (45 MMA/warp), R14 counter sync.
// Warp w: col-tile t = w&3 (8 cols), K-quarter kq = w>>2 (64 k-floats).
// =====================================================================
__global__ void __launch_bounds__(THREADS, 1) k_rec(
    const float* __restrict__ input,
    const float* __restrict__ hidden,  // [1][B][3]
    const float* __restrict__ W_dec,   // [H][3]
    const float* __restrict__ b_dec,   // [H]
    const float* __restrict__ W_ih,    // [3H][I]
    const float* __restrict__ W_hh,    // [3H][H]
    const float* __restrict__ b_ih,    // [3H]
    const float* __restrict__ b_hh)    // [3H]
{
    extern __shared__ unsigned int smu[];
    float* smf = (float*)smu;
    const uint32_t sbase = smem_u32(smu);

    const int tid = threadIdx.x;
    const int lane = tid & 31;
    const int warp = tid >> 5;
    const int t = warp & 3;           // col tile (8 cols)
    const int kq = warp >> 2;         // K quarter (0..3)
    const int grp = blockIdx.x >> 3;
    const int jc = blockIdx.x & 7;
    const int rbase = grp * ROWS;

    unsigned int* my_arr = &g_arr[grp * 32];

    // --- B fragments: hi in registers, lo in smem ---
    uint32_t bh_h[3][4][2];
    uint32_t bh_x[3][2];
    {
        const int ncol = jc * 32 + t * 8 + (lane >> 2);
        const int ql = lane & 3;
        #pragma unroll
        for (int g = 0; g < 3; g++) {
            #pragma unroll
            for (int cc = 0; cc < 4; cc++) {
                const float* wr = W_hh + (size_t)(g * HID + ncol) * HID + kq * 64 + cc * 16 + 2 * ql;
                float w0 = wr[0], w1 = wr[1], w2 = wr[8], w3 = wr[9];
                bh_h[g][cc][0] = packbf2(w0, w1);
                bh_h[g][cc][1] = packbf2(w2, w3);
                int bi = OFF_BLOH + (((warp * 3 + g) * 4 + cc) * 64 + lane * 2);
                smu[bi]     = packbf2(w0 - bfhi(w0), w1 - bfhi(w1));
                smu[bi + 1] = packbf2(w2 - bfhi(w2), w3 - bfhi(w3));
            }
            {
                const float* wr = W_ih + (size_t)(g * HID + ncol) * IN_DIM + kq * 16 + 2 * ql;
                float w0 = wr[0], w1 = wr[1], w2 = wr[8], w3 = wr[9];
                bh_x[g][0] = packbf2(w0, w1);
                bh_x[g][1] = packbf2(w2, w3);
                int bi = OFF_BLOX + ((warp * 3 + g) * 64 + lane * 2);
                smu[bi]     = packbf2(w0 - bfhi(w0), w1 - bfhi(w1));
                smu[bi + 1] = packbf2(w2 - bfhi(w2), w3 - bfhi(w3));
            }
        }
    }

    // gate-phase constants (meaningful for warps 0-3)
    const int grow = lane >> 2;                 // local row 0..7 (and +8)
    const int q = lane & 3;
    const int colg = jc * 32 + t * 8 + 2 * q;   // global col of D c0/c2
    const float bs_r0 = b_ih[colg]             + b_hh[colg];
    const float bs_r1 = b_ih[colg + 1]         + b_hh[colg + 1];
    const float bs_z0 = b_ih[HID + colg]       + b_hh[HID + colg];
    const float bs_z1 = b_ih[HID + colg + 1]   + b_hh[HID + colg + 1];
    const float bxn0  = b_ih[2 * HID + colg];
    const float bxn1  = b_ih[2 * HID + colg + 1];
    const float bhn0  = b_hh[2 * HID + colg];
    const float bhn1  = b_hh[2 * HID + colg + 1];
    // frag word index of owned h positions
    const int hch = jc * 2 + (t >> 1);
    const int hidx = (hch * 32 + grow * 4 + q) * 4 + 2 * (t & 1);

    // --- h0 -> g_hfrag[0]: one col-pair per thread (16 rows x 16 pairs = 256) ---
    if (tid < 256) {
        int r = tid >> 4, cp = tid & 15;
        int cg = jc * 32 + cp * 2;
        int b = rbase + r;
        float h0v = hidden[b * 3 + 0], h1v = hidden[b * 3 + 1], h2v = hidden[b * 3 + 2];
        float v0 = b_dec[cg]     + h0v * W_dec[cg * 3]       + h1v * W_dec[cg * 3 + 1]       + h2v * W_dec[cg * 3 + 2];
        float v1 = b_dec[cg + 1] + h0v * W_dec[(cg + 1) * 3] + h1v * W_dec[(cg + 1) * 3 + 1] + h2v * W_dec[(cg + 1) * 3 + 2];
        int chunk = jc * 2 + (cp >> 3);
        int q_l = cp & 3;
        int khalf = (cp >> 2) & 1;
        int idx = grp * 2048 + (chunk * 32 + (r & 7) * 4 + q_l) * 4 + (r >> 3) + 2 * khalf;
        g_hfrag_hi[0][idx] = packbf2(v0, v1);
        g_hfrag_lo[0][idx] = packbf2(v0 - bfhi(v0), v1 - bfhi(v1));
    }
    __syncthreads();
    if (warp < 4 && lane == 0) red_release(my_arr);   // 4/CTA -> 32/group

    // ---------------- time-step loop ----------------
    for (int s = 0; s < T_STEPS; s++) {
        const int buf = s & 1;
        // wait h(s)
        if (lane == 0) {
            unsigned int tgt = 32u * (unsigned int)(s + 1);
            while (ld_acq(my_arr) < tgt) { }
        }
        __syncwarp();

        // stage h (hi+lo, 16KB) + x (hi+lo, 4KB), frag layout verbatim
        {
            const uint4* shi = (const uint4*)(g_hfrag_hi[buf] + grp * 2048);   // 512 uint4
            const uint4* slo = (const uint4*)(g_hfrag_lo[buf] + grp * 2048);
            cp_async16(sbase + (OFF_HHI + tid * 4) * 4, shi + tid);
            cp_async16(sbase + (OFF_HLO + tid * 4) * 4, slo + tid);
            if (tid < 128) {
                const uint4* xhi = (const uint4*)(g_xfrag_hi + ((size_t)s * GROUPS + grp) * 512);
                cp_async16(sbase + (OFF_XHI + tid * 4) * 4, xhi + tid);
            } else if (tid < 256) {
                const uint4* xlo = (const uint4*)(g_xfrag_lo + ((size_t)s * GROUPS + grp) * 512);
                cp_async16(sbase + (OFF_XLO + (tid - 128) * 4) * 4, xlo + (tid - 128));
            }
        }
        cp_async_commit_wait();
        __syncthreads();

        // --- mma: 3-product bf16 chains, K quarter kq ---
        float dr[4] = {0.f, 0.f, 0.f, 0.f};
        float dz[4] = {0.f, 0.f, 0.f, 0.f};
        float dnh[4] = {0.f, 0.f, 0.f, 0.f};
        float dnx[4] = {0.f, 0.f, 0.f, 0.f};

        const uint4* Ahh = (const uint4*)(smu + OFF_HHI);
        const uint4* Ahl = (const uint4*)(smu + OFF_HLO);
        #pragma unroll
        for (int cc = 0; cc < 4; cc++) {
            int ai = (kq * 4 + cc) * 32 + lane;
            uint4 ah = Ahh[ai];
            uint4 al = Ahl[ai];
            {
                uint2 bl = *(const uint2*)(smu + OFF_BLOH + (((warp * 3 + 0) * 4 + cc) * 64 + lane * 2));
                MMA16(dr, ah, bh_h[0][cc][0], bh_h[0][cc][1]);
                MMA16(dr, al, bh_h[0][cc][0], bh_h[0][cc][1]);
                MMA16(dr, ah, bl.x, bl.y);
            }
            {
                uint2 bl = *(const uint2*)(smu + OFF_BLOH + (((warp * 3 + 1) * 4 + cc) * 64 + lane * 2));
                MMA16(dz, ah, bh_h[1][cc][0], bh_h[1][cc][1]);
                MMA16(dz, al, bh_h[1][cc][0], bh_h[1][cc][1]);
                MMA16(dz, ah, bl.x, bl.y);
            }
            {
                uint2 bl = *(const uint2*)(smu + OFF_BLOH + (((warp * 3 + 2) * 4 + cc) * 64 + lane * 2));
                MMA16(dnh, ah, bh_h[2][cc][0], bh_h[2][cc][1]);
                MMA16(dnh, al, bh_h[2][cc][0], bh_h[2][cc][1]);
                MMA16(dnh, ah, bl.x, bl.y);
            }
        }
        {
            int ai = kq * 32 + lane;
            uint4 ah = ((const uint4*)(smu + OFF_XHI))[ai];
            uint4 al = ((const uint4*)(smu + OFF_XLO))[ai];
            #pragma unroll
            for (int g = 0; g < 3; g++) {
                float* D = (g == 0) ? dr : (g == 1) ? dz : dnx;
                uint2 bl = *(const uint2*)(smu + OFF_BLOX + ((warp * 3 + g) * 64 + lane * 2));
                MMA16(D, ah, bh_x[g][0], bh_x[g][1]);
                MMA16(D, al, bh_x[g][0], bh_x[g][1]);
                MMA16(D, ah, bl.x, bl.y);
            }
        }

        // --- cross-K reduction: warps with kq>0 export partials ---
        if (kq > 0) {
            float* pp = smf + OFF_PART + (((kq - 1) * 128) + t * 32 + lane) * 20;
            *(float4*)(pp)      = make_float4(dr[0], dr[1], dr[2], dr[3]);
            *(float4*)(pp + 4)  = make_float4(dz[0], dz[1], dz[2], dz[3]);
            *(float4*)(pp + 8)  = make_float4(dnh[0], dnh[1], dnh[2], dnh[3]);
            *(float4*)(pp + 12) = make_float4(dnx[0], dnx[1], dnx[2], dnx[3]);
        }
        __syncthreads();

        if (warp < 4) {
            #pragma unroll
            for (int ps = 0; ps < 3; ps++) {
                const float* pp = smf + OFF_PART + ((ps * 128) + t * 32 + lane) * 20;
                float4 pr = *(const float4*)(pp);
                float4 pz = *(const float4*)(pp + 4);
                float4 pn = *(const float4*)(pp + 8);
                float4 px = *(const float4*)(pp + 12);
                dr[0] += pr.x; dr[1] += pr.y; dr[2] += pr.z; dr[3] += pr.w;
                dz[0] += pz.x; dz[1] += pz.y; dz[2] += pz.z; dz[3] += pz.w;
                dnh[0] += pn.x; dnh[1] += pn.y; dnh[2] += pn.z; dnh[3] += pn.w;
                dnx[0] += px.x; dnx[1] += px.y; dnx[2] += px.z; dnx[3] += px.w;
            }

            // h_old (4 positions) from staged frag tiles
            uint2 uh = *(const uint2*)(smu + OFF_HHI + hidx);
            uint2 ul = *(const uint2*)(smu + OFF_HLO + hidx);
            float2 h0p = unpackbf2(uh.x), h8p = unpackbf2(uh.y);
            float2 l0p = unpackbf2(ul.x), l8p = unpackbf2(ul.y);
            float hold00 = h0p.x + l0p.x;   // (grow,   colg)
            float hold01 = h0p.y + l0p.y;   // (grow,   colg+1)
            float hold10 = h8p.x + l8p.x;   // (grow+8, colg)
            float hold11 = h8p.y + l8p.y;   // (grow+8, colg+1)

            // gates
            float rg, zg, ng;
            rg = fast_sig(dr[0] + bs_r0); zg = fast_sig(dz[0] + bs_z0);
            ng = fast_tanh(dnx[0] + bxn0 + rg * (dnh[0] + bhn0));
            float hn00 = zg * (hold00 - ng) + ng;
            rg = fast_sig(dr[1] + bs_r1); zg = fast_sig(dz[1] + bs_z1);
            ng = fast_tanh(dnx[1] + bxn1 + rg * (dnh[1] + bhn1));
            float hn01 = zg * (hold01 - ng) + ng;
            rg = fast_sig(dr[2] + bs_r0); zg = fast_sig(dz[2] + bs_z0);
            ng = fast_tanh(dnx[2] + bxn0 + rg * (dnh[2] + bhn0));
            float hn10 = zg * (hold10 - ng) + ng;
            rg = fast_sig(dr[3] + bs_r1); zg = fast_sig(dz[3] + bs_z1);
            ng = fast_tanh(dnx[3] + bxn1 + rg * (dnh[3] + bhn1));
            float hn11 = zg * (hold11 - ng) + ng;

            // h_new -> frag arrays (hi/lo) for next step
            unsigned int* dhi = g_hfrag_hi[buf ^ 1] + grp * 2048;
            unsigned int* dlo = g_hfrag_lo[buf ^ 1] + grp * 2048;
            *(uint2*)(dhi + hidx) = make_uint2(packbf2(hn00, hn01), packbf2(hn10, hn11));
            *(uint2*)(dlo + hidx) = make_uint2(
                packbf2(hn00 - bfhi(hn00), hn01 - bfhi(hn01)),
                packbf2(hn10 - bfhi(hn10), hn11 - bfhi(hn11)));

            __syncwarp();
            if (lane == 0) red_release(my_arr);

            // trajectory (off critical path)
            float* hd = g_hs + ((size_t)s * BATCH + rbase + grow) * HID + colg;
            *(float2*)hd = make_float2(hn00, hn01);
            *(float2*)(hd + 8 * HID) = make_float2(hn10, hn11);
        }
    }

    // counter reset for next graph replay
    if (jc == 0 && tid == 0) {
        unsigned int fin = 32u * (unsigned int)(T_STEPS + 1);
        while (ld_acq(my_arr) < fin) { }
        *my_arr = 0u;
        __threadfence();
    }
}

// =====================================================================
// Output GEMM (proven R3 version): 64 rows x 64 o, K=256 in 4 chunks
// =====================================================================
#define XPITCH 68
__global__ void __launch_bounds__(256) k_out(
    const float* __restrict__ W_out,   // [I][H]
    const float* __restrict__ b_out,   // [I]
    float* __restrict__ out)           // [B][T][I]
{
    __shared__ float hs_s[64 * XPITCH];
    __shared__ float ws_s[64 * XPITCH];
    const int tid = threadIdx.x;
    const int tx = tid & 15, ty = tid >> 4;
    const size_t mbase = (size_t)blockIdx.x * 64;

    ull acc[4][4];
    #pragma unroll
    for (int ii = 0; ii < 4; ii++)
        #pragma unroll
        for (int jj = 0; jj < 4; jj++) acc[ii][jj] = 0ULL;

    for (int kc = 0; kc < 4; kc++) {
        const int kofs = kc * 64;
        for (int i = tid; i < 1024; i += 256) {
            int row = i >> 4, c = i & 15;
            float4 v = *(const float4*)(g_hs + (mbase + row) * HID + kofs + c * 4);
            *(float4*)(hs_s + row * XPITCH + c * 4) = v;
        }
        for (int i = tid; i < 1024; i += 256) {
            int row = i >> 4, c = i & 15;
            float4 v = *(const float4*)(W_out + (size_t)row * HID + kofs + c * 4);
            *(float4*)(ws_s + row * XPITCH + c * 4) = v;
        }
        __syncthreads();
        #pragma unroll
        for (int k4 = 0; k4 < 16; k4++) {
            ulonglong2 a[4], w[4];
            #pragma unroll
            for (int ii = 0; ii < 4; ii++)
                a[ii] = *(const ulonglong2*)(hs_s + (ty * 4 + ii) * XPITCH + k4 * 4);
            #pragma unroll
            for (int jj = 0; jj < 4; jj++)
                w[jj] = *(const ulonglong2*)(ws_s + (jj * 16 + tx) * XPITCH + k4 * 4);
            #pragma unroll
            for (int ii = 0; ii < 4; ii++)
                #pragma unroll
                for (int jj = 0; jj < 4; jj++) {
                    fma2(acc[ii][jj], a[ii].x, w[jj].x);
                    fma2(acc[ii][jj], a[ii].y, w[jj].y);
                }
        }
        __syncthreads();
    }

    #pragma unroll
    for (int ii = 0; ii < 4; ii++) {
        size_t m = mbase + ty * 4 + ii;
        size_t tt = m >> 8;
        size_t b = m & 255;
        float* op = out + (b * T_STEPS + tt) * IN_DIM;
        #pragma unroll
        for (int jj = 0; jj < 4; jj++) {
            int o = jj * 16 + tx;
            op[o] = redpair(acc[ii][jj]) + b_out[o];
        }
    }
}

extern "C" void kernel_launch(void* const* d_in, const int* in_sizes, int n_in,
                              void* d_out, int out_size)
{
    const float* input  = (const float*)d_in[0];
    const float* hidden = (const float*)d_in[1];
    const float* W_dec  = (const float*)d_in[2];
    const float* b_dec  = (const float*)d_in[3];
    const float* W_ih   = (const float*)d_in[4];
    const float* W_hh   = (const float*)d_in[5];
    const float* b_ih   = (const float*)d_in[6];
    const float* b_hh   = (const float*)d_in[7];
    const float* W_out  = (const float*)d_in[8];
    const float* b_out  = (const float*)d_in[9];
    float* out = (float*)d_out;

    cudaFuncSetAttribute(k_rec, cudaFuncAttributeMaxDynamicSharedMemorySize, SMEM_BYTES);

    k_xprep<<<(T_STEPS * BATCH * 16) / 256, 256>>>(input);
    k_rec<<<GROUPS * JCTAS, THREADS, SMEM_BYTES>>>(input, hidden, W_dec, b_dec,
                                                   W_ih, W_hh, b_ih, b_hh);
    k_out<<<(T_STEPS * BATCH) / 64, 256>>>(W_out, b_out, out);
}